// round 6
// baseline (speedup 1.0000x reference)
#include <cuda_runtime.h>
#include <cuda_bf16.h>
#include <cstdint>

// Problem constants
#define V_  20000
#define M_  32
#define E_  128
#define H_  4
#define N_  8192
#define L_  64
#define C_  128
#define WPB 2          // words per block in word_embed kernel
#define CNEWS 4        // news per block in conv kernel

// conv doc tile geometry (unswizzled, bank-conflict-free stride)
#define DSTRIDE 132            // floats per row (132 mod 32 = 4 -> conflict-free)
#define DOCROWS 68             // 64 + 4 pad rows (pads only feed discarded t)
#define DOCN   (DOCROWS * DSTRIDE)

// ---------------- device scratch (no allocations allowed) ----------------
__device__ float g_word_embeds[V_ * E_];          // [V,E]
__device__ float g_wqT[E_ * E_];                  // [e][i] = Wq[i][e]
__device__ float g_wvT[E_ * E_];                  // [e][i] = Wv[i][e]
__device__ float g_woT[E_ * E_];                  // [e][i] = out_w[i][e]
__device__ float g_fcT[3 * C_ * E_];              // [i][c] = fc_w[c][i]
// fragment-packed tf32 conv weights: per kstep s: 8 ntile-pairs x 32 lanes x uint4
__device__ uint4 g_wmma[49152];
#define WOFF3 0
#define WOFF4 12288
#define WOFF5 28672

// ---------------- tf32 / async helpers ----------------
__device__ __forceinline__ uint32_t f2tf32(float x) {
    uint32_t u;
    asm("cvt.rna.tf32.f32 %0, %1;" : "=r"(u) : "f"(x));
    return u;
}

__device__ __forceinline__ void mma_tf32(float* d,
                                         uint32_t a0, uint32_t a1, uint32_t a2, uint32_t a3,
                                         uint32_t b0, uint32_t b1) {
    asm volatile(
        "mma.sync.aligned.m16n8k8.row.col.f32.tf32.tf32.f32 "
        "{%0,%1,%2,%3}, {%4,%5,%6,%7}, {%8,%9}, {%0,%1,%2,%3};"
        : "+f"(d[0]), "+f"(d[1]), "+f"(d[2]), "+f"(d[3])
        : "r"(a0), "r"(a1), "r"(a2), "r"(a3), "r"(b0), "r"(b1));
}

__device__ __forceinline__ void cpa16(void* dst_smem, const void* src_gmem) {
    uint32_t d = (uint32_t)__cvta_generic_to_shared(dst_smem);
    asm volatile("cp.async.cg.shared.global [%0], [%1], 16;" :: "r"(d), "l"(src_gmem));
}
#define CPA_COMMIT() asm volatile("cp.async.commit_group;")
#define CPA_WAIT0()  asm volatile("cp.async.wait_group 0;")

// ---------------- unified prep kernel (one launch) ----------------
// segments: wqT | wvT | woT | fcT | wmma3 | wmma4 | wmma5
#define PSEG0 (E_ * E_)
#define PSEG3 (3 * C_ * E_)
#define PW3   (3 * 16 * 1024)
#define PW4   (4 * 16 * 1024)
#define PW5   (5 * 16 * 1024)
#define PREP_TOTAL (3 * PSEG0 + PSEG3 + PW3 + PW4 + PW5)

__device__ __forceinline__ void prep_wmma_one(const float* __restrict__ w, int K,
                                              int dst_off_u4, int idx) {
    int s    = idx >> 10;
    int rem  = idx & 1023;
    int p    = rem >> 7;
    int lane = (rem >> 2) & 31;
    int q    = rem & 3;
    int j  = s >> 4, ec = s & 15;
    int nt = 2 * p + (q >> 1);
    int kk = (lane & 3) + 4 * (q & 1);
    int c  = nt * 8 + (lane >> 2);
    int e  = ec * 8 + kk;
    float v = w[(c * E_ + e) * K + j];
    reinterpret_cast<uint32_t*>(g_wmma)[dst_off_u4 * 4 + idx] = f2tf32(v);
}

__global__ void prep_all_kernel(const float* __restrict__ in_w,
                                const float* __restrict__ out_w,
                                const float* __restrict__ fc_w,
                                const float* __restrict__ w3,
                                const float* __restrict__ w4,
                                const float* __restrict__ w5) {
    int idx = blockIdx.x * blockDim.x + threadIdx.x;
    if (idx >= PREP_TOTAL) return;
    if (idx < PSEG0) {                                    // wqT
        int e = idx >> 7, i = idx & 127;
        g_wqT[idx] = in_w[i * E_ + e];
        return;
    }
    idx -= PSEG0;
    if (idx < PSEG0) {                                    // wvT (Wv rows 256..383)
        int e = idx >> 7, i = idx & 127;
        g_wvT[idx] = in_w[2 * E_ * E_ + i * E_ + e];
        return;
    }
    idx -= PSEG0;
    if (idx < PSEG0) {                                    // woT
        int e = idx >> 7, i = idx & 127;
        g_woT[idx] = out_w[i * E_ + e];
        return;
    }
    idx -= PSEG0;
    if (idx < PSEG3) {                                    // fcT
        int i = idx >> 7, c = idx & 127;
        g_fcT[idx] = fc_w[c * (3 * C_) + i];
        return;
    }
    idx -= PSEG3;
    if (idx < PW3) { prep_wmma_one(w3, 3, WOFF3, idx); return; }
    idx -= PW3;
    if (idx < PW4) { prep_wmma_one(w4, 4, WOFF4, idx); return; }
    idx -= PW4;
    prep_wmma_one(w5, 5, WOFF5, idx);
}

// ---------------- word embedding kernel: 2 words per block ----------------
struct WSmem {
    float ctx[WPB][M_][E_ + 1];
    float q[WPB][E_];
    float qh[WPB][E_];
    float g[WPB][H_][E_];
    float ch[WPB][H_][E_];
    float o[WPB][E_];
    float attn[WPB][H_][M_];
    float cb[WPB][H_];
    int   idx[WPB][M_];
    int   len[WPB];
};

__global__ __launch_bounds__(128) void word_embed_kernel(
    const int* __restrict__ word2news, const int* __restrict__ word2news_len,
    const float* __restrict__ table,
    const float* __restrict__ in_w, const float* __restrict__ in_b,
    const float* __restrict__ out_b,
    const float* __restrict__ wqT, const float* __restrict__ wvT,
    const float* __restrict__ woT)
{
    extern __shared__ char smem_raw[];
    WSmem& s = *reinterpret_cast<WSmem*>(smem_raw);

    const int v0 = blockIdx.x * WPB;
    const int tid = threadIdx.x;

    if (tid < WPB * M_) {
        int w = tid >> 5, m = tid & 31;
        s.idx[w][m] = word2news[(v0 + w) * M_ + m];
    }
    if (tid < WPB) s.len[tid] = word2news_len[v0 + tid];
    __syncthreads();

    #pragma unroll
    for (int w = 0; w < WPB; ++w)
        #pragma unroll 4
        for (int m = 0; m < M_; ++m)
            s.ctx[w][m][tid] = table[s.idx[w][m] * E_ + tid];
    __syncthreads();

    // masked mean query
    #pragma unroll
    for (int w = 0; w < WPB; ++w) {
        int len = s.len[w];
        float inv = 1.0f / (float)(len > 0 ? len : 1);
        float a = 0.0f;
        for (int m = 0; m < len; ++m) a += s.ctx[w][m][tid];
        s.q[w][tid] = a * inv;
    }
    __syncthreads();

    // qh = q @ Wq^T + bq
    {
        float acc[WPB];
        #pragma unroll
        for (int w = 0; w < WPB; ++w) acc[w] = 0.0f;
        #pragma unroll 4
        for (int e = 0; e < E_; ++e) {
            float wq = wqT[e * E_ + tid];
            #pragma unroll
            for (int w = 0; w < WPB; ++w) acc[w] += s.q[w][e] * wq;
        }
        float bq = in_b[tid];
        #pragma unroll
        for (int w = 0; w < WPB; ++w) s.qh[w][tid] = acc[w] + bq;
    }
    __syncthreads();

    // g_h[e] = sum_d qh[h*32+d] * Wk[h*32+d][e]
    #pragma unroll
    for (int h = 0; h < H_; ++h) {
        float acc[WPB];
        #pragma unroll
        for (int w = 0; w < WPB; ++w) acc[w] = 0.0f;
        #pragma unroll 4
        for (int d = 0; d < 32; ++d) {
            float wk = in_w[(E_ + h * 32 + d) * E_ + tid];
            #pragma unroll
            for (int w = 0; w < WPB; ++w) acc[w] += s.qh[w][h * 32 + d] * wk;
        }
        #pragma unroll
        for (int w = 0; w < WPB; ++w) s.g[w][h][tid] = acc[w];
    }
    if (tid < WPB * H_) {
        int w = tid >> 2, h = tid & 3;
        float c = 0.0f;
        for (int d = 0; d < 32; ++d) c += s.qh[w][h * 32 + d] * in_b[E_ + h * 32 + d];
        s.cb[w][h] = c;
    }
    __syncthreads();

    // scores + per-head warp softmax
    {
        const int h = tid >> 5, m = tid & 31;
        #pragma unroll
        for (int w = 0; w < WPB; ++w) {
            float sc = s.cb[w][h];
            #pragma unroll 8
            for (int e = 0; e < E_; ++e) sc += s.ctx[w][m][e] * s.g[w][h][e];
            sc *= 0.17677669529663688f;               // 1/sqrt(32)
            if (m >= s.len[w]) sc = -1e30f;
            float wm = sc;
            #pragma unroll
            for (int o = 16; o; o >>= 1) wm = fmaxf(wm, __shfl_xor_sync(0xFFFFFFFFu, wm, o));
            float p = __expf(sc - wm);
            float ps = p;
            #pragma unroll
            for (int o = 16; o; o >>= 1) ps += __shfl_xor_sync(0xFFFFFFFFu, ps, o);
            s.attn[w][h][m] = p / ps;
        }
    }
    __syncthreads();

    // ch_h[e] = sum_m attn[h,m]*ctx[m][e]
    #pragma unroll
    for (int w = 0; w < WPB; ++w)
        #pragma unroll
        for (int h = 0; h < H_; ++h) {
            float c = 0.0f;
            #pragma unroll 8
            for (int m = 0; m < M_; ++m) c += s.attn[w][h][m] * s.ctx[w][m][tid];
            s.ch[w][h][tid] = c;
        }
    __syncthreads();

    // o[i] = ch_{h(i)} . Wv[i] + bv[i]
    {
        const int h = tid >> 5;
        float acc[WPB];
        #pragma unroll
        for (int w = 0; w < WPB; ++w) acc[w] = 0.0f;
        #pragma unroll 4
        for (int e = 0; e < E_; ++e) {
            float wv = wvT[e * E_ + tid];
            #pragma unroll
            for (int w = 0; w < WPB; ++w) acc[w] += s.ch[w][h][e] * wv;
        }
        float bv = in_b[2 * E_ + tid];
        #pragma unroll
        for (int w = 0; w < WPB; ++w) s.o[w][tid] = acc[w] + bv;
    }
    __syncthreads();

    // out proj
    {
        float acc[WPB];
        #pragma unroll
        for (int w = 0; w < WPB; ++w) acc[w] = 0.0f;
        #pragma unroll 4
        for (int e = 0; e < E_; ++e) {
            float wo = woT[e * E_ + tid];
            #pragma unroll
            for (int w = 0; w < WPB; ++w) acc[w] += s.o[w][e] * wo;
        }
        float ob = out_b[tid];
        #pragma unroll
        for (int w = 0; w < WPB; ++w)
            g_word_embeds[(v0 + w) * E_ + tid] = (s.len[w] > 0) ? (acc[w] + ob) : 0.0f;
    }
}

// ---------------- conv (tf32 mma) + maxpool + FC: 4 news per block ----------
// 256 threads = 8 warps; warp w: news = w>>1, t-half = w&1.
// B weights smem-staged per k-step (4KB chunk), double-buffered via cp.async.
template <int K>
__device__ __forceinline__ void conv_mma_phase(
    const uint4* __restrict__ Bg, const float* __restrict__ bias,
    uint4* Bbuf, const uint32_t* __restrict__ doc,
    float* pp, float* feats, int kidx, int tid)
{
    const int lane = tid & 31, warp = tid >> 5;
    const int news = warp >> 1;
    const int tb = (warp & 1) * 32;
    const uint32_t* dbase = doc + news * DOCN;
    constexpr int S = K * 16;

    float d[2][16][4];
    #pragma unroll
    for (int mt = 0; mt < 2; ++mt)
        #pragma unroll
        for (int nt = 0; nt < 16; ++nt)
            #pragma unroll
            for (int k = 0; k < 4; ++k) d[mt][nt][k] = 0.0f;

    // preload chunk 0
    cpa16(&Bbuf[tid], &Bg[tid]);
    CPA_COMMIT();
    CPA_WAIT0();
    __syncthreads();

    for (int s = 0; s < S; ++s) {
        if (s + 1 < S) {
            cpa16(&Bbuf[((s + 1) & 1) * 256 + tid], &Bg[(s + 1) * 256 + tid]);
            CPA_COMMIT();
        }
        const int j = s >> 4, ec = s & 15;
        const uint32_t* dp = dbase + (tb + j + (lane >> 2)) * DSTRIDE + ec * 8 + (lane & 3);
        uint32_t a[2][4];
        #pragma unroll
        for (int mt = 0; mt < 2; ++mt) {
            a[mt][0] = dp[(16 * mt) * DSTRIDE];
            a[mt][1] = dp[(16 * mt + 8) * DSTRIDE];
            a[mt][2] = dp[(16 * mt) * DSTRIDE + 4];
            a[mt][3] = dp[(16 * mt + 8) * DSTRIDE + 4];
        }
        const uint4* bp = Bbuf + (s & 1) * 256 + lane;
        #pragma unroll
        for (int p = 0; p < 8; ++p) {
            uint4 bb = bp[p * 32];
            mma_tf32(d[0][2 * p],     a[0][0], a[0][1], a[0][2], a[0][3], bb.x, bb.y);
            mma_tf32(d[1][2 * p],     a[1][0], a[1][1], a[1][2], a[1][3], bb.x, bb.y);
            mma_tf32(d[0][2 * p + 1], a[0][0], a[0][1], a[0][2], a[0][3], bb.z, bb.w);
            mma_tf32(d[1][2 * p + 1], a[1][0], a[1][1], a[1][2], a[1][3], bb.z, bb.w);
        }
        CPA_WAIT0();
        __syncthreads();
    }

    // max over valid t within warp, then across lane-groups
    constexpr int T = L_ - K + 1;
    #pragma unroll
    for (int nt = 0; nt < 16; ++nt)
        #pragma unroll
        for (int r = 0; r < 2; ++r) {
            float m = -1e30f;
            #pragma unroll
            for (int mt = 0; mt < 2; ++mt)
                #pragma unroll
                for (int rr = 0; rr < 2; ++rr) {
                    int tl = tb + 16 * mt + (lane >> 2) + 8 * rr;
                    if (tl < T) m = fmaxf(m, d[mt][nt][2 * rr + r]);
                }
            m = fmaxf(m, __shfl_xor_sync(0xFFFFFFFFu, m, 4));
            m = fmaxf(m, __shfl_xor_sync(0xFFFFFFFFu, m, 8));
            m = fmaxf(m, __shfl_xor_sync(0xFFFFFFFFu, m, 16));
            if (lane < 4) pp[warp * 128 + nt * 8 + 2 * lane + r] = m;
        }
    __syncthreads();
    {
        const int c = tid & 127;
        #pragma unroll
        for (int pass = 0; pass < 2; ++pass) {
            int bn = pass * 2 + (tid >> 7);
            float v = fmaxf(pp[(2 * bn) * 128 + c], pp[(2 * bn + 1) * 128 + c]);
            feats[bn * 384 + kidx * 128 + c] = fmaxf(v + bias[c], 0.0f);
        }
    }
    __syncthreads();
}

__global__ __launch_bounds__(256, 1) void conv_mma_kernel(
    const int* __restrict__ news_words,
    const float* __restrict__ b3, const float* __restrict__ b4, const float* __restrict__ b5,
    const float* __restrict__ fcT, const float* __restrict__ fc_b,
    float* __restrict__ out)
{
    extern __shared__ uint4 smem4[];
    uint4*    Bbuf  = smem4;                            // 512 uint4 (double buffer)
    uint32_t* doc   = (uint32_t*)(smem4 + 512);         // 4*DOCN
    float*    pp    = (float*)(doc + CNEWS * DOCN);     // 8*128
    float*    feats = pp + 1024;                        // 4*384
    int*      idx   = (int*)(feats + CNEWS * 384);      // 256

    const int n0 = blockIdx.x * CNEWS;
    const int tid = threadIdx.x;

    idx[tid] = news_words[n0 * L_ + tid];               // 4*64 = 256 indices
    __syncthreads();

    // gather doc rows: 256 rows total (news b = r>>6, row l = r&63)
    {
        const int col = tid & 127;
        const int ro  = tid >> 7;
        #pragma unroll 4
        for (int r2 = 0; r2 < 128; ++r2) {
            int r = r2 * 2 + ro;
            int b = r >> 6, l = r & 63;
            float v = g_word_embeds[idx[r] * E_ + col];
            doc[b * DOCN + l * DSTRIDE + col] = f2tf32(v);
        }
        // zero pad rows 64..67 of each news
        for (int i = tid; i < CNEWS * 4 * DSTRIDE; i += 256) {
            int b = i / (4 * DSTRIDE);
            int rem = i - b * (4 * DSTRIDE);
            doc[b * DOCN + 64 * DSTRIDE + rem] = 0;
        }
    }
    __syncthreads();

    conv_mma_phase<3>(g_wmma + WOFF3, b3, Bbuf, doc, pp, feats, 0, tid);
    conv_mma_phase<4>(g_wmma + WOFF4, b4, Bbuf, doc, pp, feats, 1, tid);
    conv_mma_phase<5>(g_wmma + WOFF5, b5, Bbuf, doc, pp, feats, 2, tid);

    // FC epilogue: out[n, i] = fc_b[i] + feats . fcT[:, i]
    {
        const int i = tid & 127;
        #pragma unroll
        for (int pass = 0; pass < 2; ++pass) {
            int bn = pass * 2 + (tid >> 7);
            float acc = fc_b[i];
            #pragma unroll 8
            for (int k = 0; k < 3 * C_; ++k) acc += feats[bn * 384 + k] * fcT[k * E_ + i];
            out[(n0 + bn) * E_ + i] = acc;
        }
    }
}

// ---------------- launch ----------------
extern "C" void kernel_launch(void* const* d_in, const int* in_sizes, int n_in,
                              void* d_out, int out_size) {
    const int*   word2news     = (const int*)d_in[0];
    const int*   word2news_len = (const int*)d_in[1];
    const int*   news_words    = (const int*)d_in[2];
    const float* table         = (const float*)d_in[3];
    const float* in_w          = (const float*)d_in[4];
    const float* in_b          = (const float*)d_in[5];
    const float* out_w         = (const float*)d_in[6];
    const float* out_b         = (const float*)d_in[7];
    const float* w3            = (const float*)d_in[8];
    const float* b3            = (const float*)d_in[9];
    const float* w4            = (const float*)d_in[10];
    const float* b4            = (const float*)d_in[11];
    const float* w5            = (const float*)d_in[12];
    const float* b5            = (const float*)d_in[13];
    const float* fc_w          = (const float*)d_in[14];
    const float* fc_b          = (const float*)d_in[15];
    float* out = (float*)d_out;

    float *wqT, *wvT, *woT, *fcT;
    cudaGetSymbolAddress((void**)&wqT, g_wqT);
    cudaGetSymbolAddress((void**)&wvT, g_wvT);
    cudaGetSymbolAddress((void**)&woT, g_woT);
    cudaGetSymbolAddress((void**)&fcT, g_fcT);

    const int word_smem = (int)sizeof(WSmem);
    const int conv_smem = (512 * 16) + (CNEWS * DOCN * 4) + (1024 * 4)
                        + (CNEWS * 384 * 4) + (256 * 4);   // ~163 KB
    cudaFuncSetAttribute(word_embed_kernel,
                         cudaFuncAttributeMaxDynamicSharedMemorySize, word_smem);
    cudaFuncSetAttribute(conv_mma_kernel,
                         cudaFuncAttributeMaxDynamicSharedMemorySize, conv_smem);

    prep_all_kernel<<<(PREP_TOTAL + 255) / 256, 256>>>(in_w, out_w, fc_w, w3, w4, w5);

    word_embed_kernel<<<V_ / WPB, 128, word_smem>>>(
        word2news, word2news_len, table, in_w, in_b, out_b, wqT, wvT, woT);

    conv_mma_kernel<<<N_ / CNEWS, 256, conv_smem>>>(news_words, b3, b4, b5, fcT, fc_b, out);
}